// round 3
// baseline (speedup 1.0000x reference)
#include <cuda_runtime.h>
#include <cuda_bf16.h>

// VectorQuantizer (per-dimension scalar codebooks), single fused kernel.
//   z:         [B, D]  float32   (B=2048, D=128)
//   codebooks: [D, K]  float32   (K=512)
// Per (b,d): nearest code via sorted codebook + (register-pivot) binary search.

#define VQ_D 128
#define VQ_K 512
#define VQ_THREADS 256
#define VQ_BPT 2
#define VQ_CHUNK_B (VQ_THREADS * VQ_BPT)   // 512 batch elems per block
#define PADIDX(i) ((i) + ((i) >> 5))       // bank-deswizzle for pow2 strides

__device__ float        g_partials[1024];
__device__ unsigned int g_count = 0;

__global__ void __launch_bounds__(VQ_THREADS)
vq_fused_kernel(const float* __restrict__ z,
                const float* __restrict__ cb,
                float* __restrict__ qout,      // may be null
                float* __restrict__ loss_out,  // may be null
                int nb, float inv_n)
{
    __shared__ float s[VQ_K];
    __shared__ float ss[VQ_K + (VQ_K >> 5)];   // padded sorted copy
    __shared__ float swred[VQ_THREADS / 32];
    __shared__ float sblock;
    __shared__ int   s_is_last;

    const int d    = blockIdx.x;
    const int tid  = threadIdx.x;
    const int lane = tid & 31;
    const int wid  = tid >> 5;

    // ---- prefetch z (latency hides under the sort) ----
    const int bbase = blockIdx.y * VQ_CHUNK_B;
    const int b0 = bbase + tid;
    const int b1 = bbase + VQ_THREADS + tid;
    const bool v0 = (b0 < nb), v1 = (b1 < nb);
    float zv0 = v0 ? z[b0 * VQ_D + d] : 0.0f;
    float zv1 = v1 ? z[b1 * VQ_D + d] : 0.0f;

    // ---- stage codebook row d ----
    if (tid < VQ_K / 4) {
        reinterpret_cast<float4*>(s)[tid] =
            reinterpret_cast<const float4*>(cb + d * VQ_K)[tid];
    }

    // ---- bitonic sort ascending ----
    for (int k = 2; k <= VQ_K; k <<= 1) {
        for (int j = k >> 1; j > 0; j >>= 1) {
            __syncthreads();
#pragma unroll
            for (int t = 0; t < VQ_K / VQ_THREADS; t++) {
                int i   = tid + t * VQ_THREADS;
                int ixj = i ^ j;
                if (ixj > i) {
                    float a = s[i], b = s[ixj];
                    bool up = ((i & k) == 0);
                    if ((a > b) == up) { s[i] = b; s[ixj] = a; }
                }
            }
        }
    }
    __syncthreads();

    // ---- padded copy + register pivots ----
#pragma unroll
    for (int t = 0; t < VQ_K / VQ_THREADS; t++) {
        int i = tid + t * VQ_THREADS;
        ss[PADIDX(i)] = s[i];
    }
    // broadcast pivot loads (no conflicts)
    const float p255 = s[255];
    const float p127 = s[127], p383 = s[383];
    const float p63  = s[63],  p191 = s[191], p319 = s[319], p447 = s[447];
    const float q0 = s[31],  q1 = s[95],  q2 = s[159], q3 = s[223];
    const float q4 = s[287], q5 = s[351], q6 = s[415], q7 = s[479];
    __syncthreads();

    // ---- search lambda (lower_bound: pos = #codes < zv) ----
    auto nearest = [&](float zv) -> float {
        // levels 256/128/64/32 on registers
        bool c0 = p255 < zv;
        float t1 = c0 ? p383 : p127;
        bool c1 = t1 < zv;
        float t2 = c0 ? (c1 ? p447 : p319) : (c1 ? p191 : p63);
        bool c2 = t2 < zv;
        float t3 = c0 ? (c1 ? (c2 ? q7 : q6) : (c2 ? q5 : q4))
                      : (c1 ? (c2 ? q3 : q2) : (c2 ? q1 : q0));
        bool c3 = t3 < zv;
        int pos = (c0 ? 256 : 0) + (c1 ? 128 : 0) + (c2 ? 64 : 0) + (c3 ? 32 : 0);
        // levels 16..1 via padded smem
#pragma unroll
        for (int step = 16; step >= 1; step >>= 1)
            if (ss[PADIDX(pos + step - 1)] < zv) pos += step;

        int li = pos > 0 ? pos - 1 : 0;
        int ri = pos < VQ_K ? pos : VQ_K - 1;
        float lv = ss[PADIDX(li)];
        float rv = ss[PADIDX(ri)];
        float dl = zv - lv, dr = rv - zv;
        float dl2 = (pos > 0)    ? dl * dl : 3.4e38f;
        float dr2 = (pos < VQ_K) ? dr * dr : 3.4e38f;
        return (dl2 <= dr2) ? lv : rv;   // squared compare, like reference
    };

    float acc = 0.0f;
    float q0v = nearest(zv0);
    float q1v = nearest(zv1);
    if (v0) {
        if (qout) qout[b0 * VQ_D + d] = zv0 + (q0v - zv0);
        float e = q0v - zv0; acc += e * e;
    }
    if (v1) {
        if (qout) qout[b1 * VQ_D + d] = zv1 + (q1v - zv1);
        float e = q1v - zv1; acc += e * e;
    }

    // ---- block loss reduction ----
#pragma unroll
    for (int o = 16; o > 0; o >>= 1)
        acc += __shfl_down_sync(0xffffffffu, acc, o);
    if (lane == 0) swred[wid] = acc;
    __syncthreads();
    if (tid == 0) {
        float t = 0.0f;
#pragma unroll
        for (int w = 0; w < VQ_THREADS / 32; w++) t += swred[w];
        sblock = t;
    }
    __syncthreads();

    // ---- cross-block finalize (last block) ----
    const int nblocks = gridDim.x * gridDim.y;
    const int bindex  = blockIdx.y * gridDim.x + blockIdx.x;
    if (tid == 0) {
        g_partials[bindex] = sblock;
        __threadfence();
        unsigned int c = atomicAdd(&g_count, 1u);
        s_is_last = (c == (unsigned int)(nblocks - 1));
    }
    __syncthreads();

    if (s_is_last && tid < 32) {
        __threadfence();
        float t = 0.0f;
        for (int i = lane; i < nblocks; i += 32)
            t += g_partials[i];
#pragma unroll
        for (int o = 16; o > 0; o >>= 1)
            t += __shfl_down_sync(0xffffffffu, t, o);
        if (lane == 0) {
            if (loss_out) *loss_out = t * inv_n;
            g_count = 0;   // reset for next graph replay
        }
    }
}

extern "C" void kernel_launch(void* const* d_in, const int* in_sizes, int n_in,
                              void* d_out, int out_size)
{
    const float* z  = (const float*)d_in[0];   // [B, D]
    const float* cb = (const float*)d_in[1];   // [D, K]
    float* out = (float*)d_out;

    const int nb       = in_sizes[0] / VQ_D;   // B
    const int bd_total = nb * VQ_D;

    float* loss_ptr = nullptr;
    float* q_ptr    = nullptr;
    if (out_size == bd_total + 1)      { loss_ptr = out; q_ptr = out + 1; }
    else if (out_size == bd_total)     { q_ptr = out; }
    else if (out_size == 1)            { loss_ptr = out; }
    else                               { q_ptr = out; }

    int chunks = (nb + VQ_CHUNK_B - 1) / VQ_CHUNK_B;
    if (chunks > 8) chunks = 8;                // g_partials bound (B=2048 -> 4)

    float inv_n = 1.0f / (float)bd_total;
    dim3 grid(VQ_D, chunks);
    vq_fused_kernel<<<grid, VQ_THREADS>>>(z, cb, q_ptr, loss_ptr, nb, inv_n);
}

// round 4
// speedup vs baseline: 1.0586x; 1.0586x over previous
#include <cuda_runtime.h>
#include <cuda_bf16.h>
#include <math_constants.h>

// VectorQuantizer (per-dimension scalar codebooks), two-phase:
//   K1: per-dim bitonic sort -> global sorted codes + Voronoi midpoints
//   K2: lower_bound on midpoints -> quantized + mean-squared loss
//   z: [B, D] f32 (B=2048, D=128); codebooks: [D, K] f32 (K=512)

#define VQ_D 128
#define VQ_K 512
#define VQ_THREADS 256
#define VQ_BPT 2
#define VQ_CHUNK_B (VQ_THREADS * VQ_BPT)   // 512 batch elems per search block
#define PADIDX(i) ((i) + ((i) >> 5))       // bank-deswizzle for pow2 strides

__device__ float        g_code[VQ_D * VQ_K];   // sorted codes
__device__ float        g_mid [VQ_D * VQ_K];   // midpoints, [511] = +INF
__device__ float        g_partials[1024];
__device__ unsigned int g_count = 0;

// ---------------- Kernel 1: sort + midpoints ----------------
__global__ void __launch_bounds__(VQ_THREADS)
vq_sort_kernel(const float* __restrict__ cb)
{
    __shared__ float s[VQ_K];
    const int d   = blockIdx.x;
    const int tid = threadIdx.x;

    if (tid < VQ_K / 4)
        reinterpret_cast<float4*>(s)[tid] =
            reinterpret_cast<const float4*>(cb + d * VQ_K)[tid];

    for (int k = 2; k <= VQ_K; k <<= 1) {
        for (int j = k >> 1; j > 0; j >>= 1) {
            __syncthreads();
#pragma unroll
            for (int t = 0; t < VQ_K / VQ_THREADS; t++) {
                int i   = tid + t * VQ_THREADS;
                int ixj = i ^ j;
                if (ixj > i) {
                    float a = s[i], b = s[ixj];
                    bool up = ((i & k) == 0);
                    if ((a > b) == up) { s[i] = b; s[ixj] = a; }
                }
            }
        }
    }
    __syncthreads();

#pragma unroll
    for (int t = 0; t < VQ_K / VQ_THREADS; t++) {
        int i = tid + t * VQ_THREADS;
        float c  = s[i];
        float cn = (i < VQ_K - 1) ? s[i + 1] : 0.0f;
        g_code[d * VQ_K + i] = c;
        g_mid [d * VQ_K + i] = (i < VQ_K - 1) ? 0.5f * (c + cn) : CUDART_INF_F;
    }
}

// ---------------- Kernel 2: search + loss ----------------
__global__ void __launch_bounds__(VQ_THREADS)
vq_search_kernel(const float* __restrict__ z,
                 float* __restrict__ qout,      // may be null
                 float* __restrict__ loss_out,  // may be null
                 int nb, float inv_n)
{
    __shared__ float sm[VQ_K + (VQ_K >> 5)];   // padded midpoints
    __shared__ float sc[VQ_K];                 // sorted codes
    __shared__ float swred[VQ_THREADS / 32];
    __shared__ float sblock;
    __shared__ int   s_is_last;

    const int d    = blockIdx.x;
    const int tid  = threadIdx.x;
    const int lane = tid & 31;
    const int wid  = tid >> 5;

    // prefetch z (latency hidden under staging)
    const int bbase = blockIdx.y * VQ_CHUNK_B;
    const int b0 = bbase + tid;
    const int b1 = bbase + VQ_THREADS + tid;
    const bool v0 = (b0 < nb), v1 = (b1 < nb);
    float zv0 = v0 ? z[b0 * VQ_D + d] : 0.0f;
    float zv1 = v1 ? z[b1 * VQ_D + d] : 0.0f;

    // stage midpoints (padded) + codes
    if (tid < VQ_K / 4) {
        float4 m = reinterpret_cast<const float4*>(g_mid + d * VQ_K)[tid];
        int i = tid * 4;
        sm[PADIDX(i + 0)] = m.x;
        sm[PADIDX(i + 1)] = m.y;
        sm[PADIDX(i + 2)] = m.z;
        sm[PADIDX(i + 3)] = m.w;
        reinterpret_cast<float4*>(sc)[tid] =
            reinterpret_cast<const float4*>(g_code + d * VQ_K)[tid];
    }
    __syncthreads();

    // register pivots (broadcast loads, conflict-free)
    const float p255 = sm[PADIDX(255)];
    const float p127 = sm[PADIDX(127)], p383 = sm[PADIDX(383)];
    const float p63  = sm[PADIDX(63)],  p191 = sm[PADIDX(191)];
    const float p319 = sm[PADIDX(319)], p447 = sm[PADIDX(447)];
    const float r0 = sm[PADIDX(31)],  r1 = sm[PADIDX(95)];
    const float r2 = sm[PADIDX(159)], r3 = sm[PADIDX(223)];
    const float r4 = sm[PADIDX(287)], r5 = sm[PADIDX(351)];
    const float r6 = sm[PADIDX(415)], r7 = sm[PADIDX(479)];

    auto nearest = [&](float zv) -> float {
        bool c0 = p255 < zv;
        float t1 = c0 ? p383 : p127;
        bool c1 = t1 < zv;
        float t2 = c0 ? (c1 ? p447 : p319) : (c1 ? p191 : p63);
        bool c2 = t2 < zv;
        float t3 = c0 ? (c1 ? (c2 ? r7 : r6) : (c2 ? r5 : r4))
                      : (c1 ? (c2 ? r3 : r2) : (c2 ? r1 : r0));
        bool c3 = t3 < zv;
        int pos = (c0 ? 256 : 0) + (c1 ? 128 : 0) + (c2 ? 64 : 0) + (c3 ? 32 : 0);
#pragma unroll
        for (int step = 16; step >= 1; step >>= 1)
            if (sm[PADIDX(pos + step - 1)] < zv) pos += step;
        return sc[pos];   // pos in [0,511]; mid[511]=+INF never counted
    };

    float acc = 0.0f;
    float q0v = nearest(zv0);
    float q1v = nearest(zv1);
    if (v0) {
        if (qout) qout[b0 * VQ_D + d] = zv0 + (q0v - zv0);
        float e = q0v - zv0; acc += e * e;
    }
    if (v1) {
        if (qout) qout[b1 * VQ_D + d] = zv1 + (q1v - zv1);
        float e = q1v - zv1; acc += e * e;
    }

    // block loss reduction (deterministic)
#pragma unroll
    for (int o = 16; o > 0; o >>= 1)
        acc += __shfl_down_sync(0xffffffffu, acc, o);
    if (lane == 0) swred[wid] = acc;
    __syncthreads();
    if (tid == 0) {
        float t = 0.0f;
#pragma unroll
        for (int w = 0; w < VQ_THREADS / 32; w++) t += swred[w];
        sblock = t;
    }
    __syncthreads();

    // cross-block finalize (last block)
    const int nblocks = gridDim.x * gridDim.y;
    const int bindex  = blockIdx.y * gridDim.x + blockIdx.x;
    if (tid == 0) {
        g_partials[bindex] = sblock;
        __threadfence();
        unsigned int c = atomicAdd(&g_count, 1u);
        s_is_last = (c == (unsigned int)(nblocks - 1));
    }
    __syncthreads();

    if (s_is_last && tid < 32) {
        __threadfence();
        float t = 0.0f;
        for (int i = lane; i < nblocks; i += 32)
            t += g_partials[i];
#pragma unroll
        for (int o = 16; o > 0; o >>= 1)
            t += __shfl_down_sync(0xffffffffu, t, o);
        if (lane == 0) {
            if (loss_out) *loss_out = t * inv_n;
            g_count = 0;   // reset for next graph replay
        }
    }
}

extern "C" void kernel_launch(void* const* d_in, const int* in_sizes, int n_in,
                              void* d_out, int out_size)
{
    const float* z  = (const float*)d_in[0];   // [B, D]
    const float* cb = (const float*)d_in[1];   // [D, K]
    float* out = (float*)d_out;

    const int nb       = in_sizes[0] / VQ_D;   // B
    const int bd_total = nb * VQ_D;

    float* loss_ptr = nullptr;
    float* q_ptr    = nullptr;
    if (out_size == bd_total + 1)      { loss_ptr = out; q_ptr = out + 1; }
    else if (out_size == bd_total)     { q_ptr = out; }
    else if (out_size == 1)            { loss_ptr = out; }
    else                               { q_ptr = out; }

    int chunks = (nb + VQ_CHUNK_B - 1) / VQ_CHUNK_B;
    if (chunks > 8) chunks = 8;                // g_partials bound (B=2048 -> 4)

    float inv_n = 1.0f / (float)bd_total;

    vq_sort_kernel<<<VQ_D, VQ_THREADS>>>(cb);
    dim3 grid(VQ_D, chunks);
    vq_search_kernel<<<grid, VQ_THREADS>>>(z, q_ptr, loss_ptr, nb, inv_n);
}

// round 6
// speedup vs baseline: 1.1267x; 1.0643x over previous
#include <cuda_runtime.h>
#include <cuda_bf16.h>
#include <math_constants.h>
#include <cstdint>

// VectorQuantizer (per-dimension scalar codebooks), two-phase:
//   K1: per-dim bitonic sort -> sorted codes + Voronoi midpoints (global scratch)
//   K2: 4-dim-grouped lower_bound on midpoints -> quantized + MSE loss
//   z: [B, D] f32 (B=2048, D=128); codebooks: [D, K] f32 (K=512)

#define VQ_D 128
#define VQ_K 512
#define VQ_THREADS 256
#define NDIMS 4                              // dims per search block
#define PADIDX(i) ((i) + ((i) >> 5))         // bank-deswizzle for pow2 strides
#define PADK (VQ_K + (VQ_K >> 5))            // 528

__device__ float4       g_code4[VQ_D * VQ_K / 4];   // sorted codes
__device__ float4       g_mid4 [VQ_D * VQ_K / 4];   // midpoints, last = +INF
__device__ float        g_partials[1024];
__device__ unsigned int g_count = 0;

// ---------------- Kernel 1: sort + midpoints ----------------
__global__ void __launch_bounds__(VQ_THREADS)
vq_sort_kernel(const float* __restrict__ cb)
{
    __shared__ float s[VQ_K];
    const int d   = blockIdx.x;
    const int tid = threadIdx.x;

    if (tid < VQ_K / 4)
        reinterpret_cast<float4*>(s)[tid] =
            reinterpret_cast<const float4*>(cb + d * VQ_K)[tid];

    for (int k = 2; k <= VQ_K; k <<= 1) {
        for (int j = k >> 1; j > 0; j >>= 1) {
            __syncthreads();
#pragma unroll
            for (int t = 0; t < VQ_K / VQ_THREADS; t++) {
                int i   = tid + t * VQ_THREADS;
                int ixj = i ^ j;
                if (ixj > i) {
                    float a = s[i], b = s[ixj];
                    bool up = ((i & k) == 0);
                    if ((a > b) == up) { s[i] = b; s[ixj] = a; }
                }
            }
        }
    }
    __syncthreads();

    float* gc = reinterpret_cast<float*>(g_code4);
    float* gm = reinterpret_cast<float*>(g_mid4);
#pragma unroll
    for (int t = 0; t < VQ_K / VQ_THREADS; t++) {
        int i = tid + t * VQ_THREADS;
        float c  = s[i];
        float cn = (i < VQ_K - 1) ? s[i + 1] : 0.0f;
        gc[d * VQ_K + i] = c;
        gm[d * VQ_K + i] = (i < VQ_K - 1) ? 0.5f * (c + cn) : CUDART_INF_F;
    }
}

// ---------------- Kernel 2: 4-dim grouped search + loss ----------------
__global__ void __launch_bounds__(VQ_THREADS)
vq_search_kernel(const float4* __restrict__ z4,
                 float* __restrict__ qout,      // may be null
                 float* __restrict__ loss_out,  // may be null
                 int nb, float inv_n, int vec_ok)
{
    __shared__ float smid [NDIMS][PADK];
    __shared__ float scode[NDIMS][PADK];
    __shared__ float swred[VQ_THREADS / 32];
    __shared__ float sblock;
    __shared__ int   s_is_last;

    const int dg   = blockIdx.x;          // dim group 0..31
    const int d0   = dg * NDIMS;
    const int tid  = threadIdx.x;
    const int lane = tid & 31;
    const int wid  = tid >> 5;

    // prefetch z (one float4 = 4 dims for one b)
    const int b = blockIdx.y * VQ_THREADS + tid;
    const bool v = (b < nb);
    float4 zv = v ? z4[b * (VQ_D / 4) + dg] : make_float4(0.f, 0.f, 0.f, 0.f);

    // stage 4 dims' midpoints (padded) + codes (padded)
#pragma unroll
    for (int i = tid; i < NDIMS * (VQ_K / 4); i += VQ_THREADS) {
        int di = i >> 7;             // 128 float4 per dim
        int e4 = i & 127;
        int e  = e4 * 4;
        float4 m = g_mid4[(d0 + di) * (VQ_K / 4) + e4];
        smid[di][PADIDX(e + 0)] = m.x;
        smid[di][PADIDX(e + 1)] = m.y;
        smid[di][PADIDX(e + 2)] = m.z;
        smid[di][PADIDX(e + 3)] = m.w;
        float4 c = g_code4[(d0 + di) * (VQ_K / 4) + e4];
        scode[di][PADIDX(e + 0)] = c.x;
        scode[di][PADIDX(e + 1)] = c.y;
        scode[di][PADIDX(e + 2)] = c.z;
        scode[di][PADIDX(e + 3)] = c.w;
    }
    __syncthreads();

    // 4 interleaved lower_bound searches (ILP hides LDS latency)
    int p0 = 0, p1 = 0, p2 = 0, p3 = 0;
#pragma unroll
    for (int step = VQ_K / 2; step >= 1; step >>= 1) {
        if (smid[0][PADIDX(p0 + step - 1)] < zv.x) p0 += step;
        if (smid[1][PADIDX(p1 + step - 1)] < zv.y) p1 += step;
        if (smid[2][PADIDX(p2 + step - 1)] < zv.z) p2 += step;
        if (smid[3][PADIDX(p3 + step - 1)] < zv.w) p3 += step;
    }
    float q0 = scode[0][PADIDX(p0)];
    float q1 = scode[1][PADIDX(p1)];
    float q2 = scode[2][PADIDX(p2)];
    float q3 = scode[3][PADIDX(p3)];

    float acc = 0.0f;
    if (v) {
        float e0 = q0 - zv.x, e1 = q1 - zv.y, e2 = q2 - zv.z, e3 = q3 - zv.w;
        acc = e0 * e0 + e1 * e1 + e2 * e2 + e3 * e3;
        if (qout) {
            // straight-through value: z + (q - z)
            float o0 = zv.x + (q0 - zv.x);
            float o1 = zv.y + (q1 - zv.y);
            float o2 = zv.z + (q2 - zv.z);
            float o3 = zv.w + (q3 - zv.w);
            if (vec_ok) {
                reinterpret_cast<float4*>(qout)[b * (VQ_D / 4) + dg] =
                    make_float4(o0, o1, o2, o3);
            } else {
                float* qp = qout + b * VQ_D + d0;
                qp[0] = o0; qp[1] = o1; qp[2] = o2; qp[3] = o3;
            }
        }
    }

    // block loss reduction (deterministic)
#pragma unroll
    for (int o = 16; o > 0; o >>= 1)
        acc += __shfl_down_sync(0xffffffffu, acc, o);
    if (lane == 0) swred[wid] = acc;
    __syncthreads();
    if (tid == 0) {
        float t = 0.0f;
#pragma unroll
        for (int w = 0; w < VQ_THREADS / 32; w++) t += swred[w];
        sblock = t;
    }
    __syncthreads();

    // cross-block finalize (last block, deterministic order)
    const int nblocks = gridDim.x * gridDim.y;
    const int bindex  = blockIdx.y * gridDim.x + blockIdx.x;
    if (tid == 0) {
        g_partials[bindex] = sblock;
        __threadfence();
        unsigned int c = atomicAdd(&g_count, 1u);
        s_is_last = (c == (unsigned int)(nblocks - 1));
    }
    __syncthreads();

    if (s_is_last && tid < 32) {
        __threadfence();
        float t = 0.0f;
        for (int i = lane; i < nblocks; i += 32)
            t += g_partials[i];
#pragma unroll
        for (int o = 16; o > 0; o >>= 1)
            t += __shfl_down_sync(0xffffffffu, t, o);
        if (lane == 0) {
            if (loss_out) *loss_out = t * inv_n;
            g_count = 0;   // reset for next graph replay
        }
    }
}

extern "C" void kernel_launch(void* const* d_in, const int* in_sizes, int n_in,
                              void* d_out, int out_size)
{
    const float* z  = (const float*)d_in[0];   // [B, D]
    const float* cb = (const float*)d_in[1];   // [D, K]
    float* out = (float*)d_out;

    const int nb       = in_sizes[0] / VQ_D;   // B
    const int bd_total = nb * VQ_D;

    float* loss_ptr = nullptr;
    float* q_ptr    = nullptr;
    if (out_size == bd_total + 1)      { loss_ptr = out; q_ptr = out + 1; }
    else if (out_size == bd_total)     { q_ptr = out; }
    else if (out_size == 1)            { loss_ptr = out; }
    else                               { q_ptr = out; }

    int chunks = (nb + VQ_THREADS - 1) / VQ_THREADS;   // 8 for B=2048
    if (chunks > 32) chunks = 32;                      // g_partials bound

    float inv_n = 1.0f / (float)bd_total;
    int vec_ok = (q_ptr != nullptr) && ((((std::uintptr_t)q_ptr) & 15) == 0);

    vq_sort_kernel<<<VQ_D, VQ_THREADS>>>(cb);
    dim3 grid(VQ_D / NDIMS, chunks);
    vq_search_kernel<<<grid, VQ_THREADS>>>(
        (const float4*)z, q_ptr, loss_ptr, nb, inv_n, vec_ok);
}